// round 15
// baseline (speedup 1.0000x reference)
#include <cuda_runtime.h>
#include <cuda_fp16.h>
#include <math.h>
#include <stdint.h>

#define D_MODEL 2048
#define NQ 32
#define NKV 8
#define HD 64
#define B_ 2
#define T_ 2048
#define ROWS (B_ * T_)
#define QKVW 3072   // Q | K | V packed row width

// Scratch (allocation-free device globals), all fp16.
__device__ __half g_xh[(size_t)ROWS * D_MODEL];        // x in half
__device__ __half g_QKVh[(size_t)ROWS * QKVW];         // Q|K|V packed
__device__ __half g_Wth[(size_t)QKVW * D_MODEL];       // Wq^T|Wk^T|Wv^T

// ============================ PTX helpers ============================
__device__ __forceinline__ uint32_t smem_u32(const void* p) {
    uint32_t a;
    asm("{ .reg .u64 t; cvta.to.shared.u64 t, %1; cvt.u32.u64 %0, t; }"
        : "=r"(a) : "l"(p));
    return a;
}
__device__ __forceinline__ uint32_t h2ex2(uint32_t x) {
    uint32_t y;
    asm("ex2.approx.f16x2 %0, %1;" : "=r"(y) : "r"(x));
    return y;
}
#define CP16(dst, src) \
    asm volatile("cp.async.cg.shared.global [%0], [%1], 16;" \
                 :: "r"(dst), "l"(src))
#define CP_COMMIT() asm volatile("cp.async.commit_group;" ::: "memory")
#define CP_WAIT0() asm volatile("cp.async.wait_group 0;" ::: "memory")
#define CP_WAIT1() asm volatile("cp.async.wait_group 1;" ::: "memory")

__device__ __forceinline__ void ldm_x4(uint32_t* r, uint32_t a) {
    asm volatile("ldmatrix.sync.aligned.m8n8.x4.shared.b16 {%0,%1,%2,%3}, [%4];"
                 : "=r"(r[0]), "=r"(r[1]), "=r"(r[2]), "=r"(r[3]) : "r"(a));
}
__device__ __forceinline__ void ldm_x4t(uint32_t* r, uint32_t a) {
    asm volatile(
        "ldmatrix.sync.aligned.m8n8.x4.trans.shared.b16 {%0,%1,%2,%3}, [%4];"
        : "=r"(r[0]), "=r"(r[1]), "=r"(r[2]), "=r"(r[3]) : "r"(a));
}
__device__ __forceinline__ void mma_f16(float* d, const uint32_t* a,
                                        const uint32_t* b) {
    asm volatile(
        "mma.sync.aligned.m16n8k16.row.col.f32.f16.f16.f32 "
        "{%0,%1,%2,%3}, {%4,%5,%6,%7}, {%8,%9}, {%0,%1,%2,%3};"
        : "+f"(d[0]), "+f"(d[1]), "+f"(d[2]), "+f"(d[3])
        : "r"(a[0]), "r"(a[1]), "r"(a[2]), "r"(a[3]), "r"(b[0]), "r"(b[1]));
}

// ============================ x -> half ============================
__global__ __launch_bounds__(256) void cvt_x(const float* __restrict__ x,
                                             __half* __restrict__ xh) {
    int i = (blockIdx.x * 256 + threadIdx.x) * 4;
    float4 v = *reinterpret_cast<const float4*>(x + i);
    *reinterpret_cast<__half2*>(xh + i) = __floats2half2_rn(v.x, v.y);
    *reinterpret_cast<__half2*>(xh + i + 2) = __floats2half2_rn(v.z, v.w);
}

// ============================ W transposes (one launch) ============================
__global__ __launch_bounds__(256) void transpose_all(
    const float* __restrict__ Wq, const float* __restrict__ Wk,
    const float* __restrict__ Wv, __half* __restrict__ Wt, float sc) {
    __shared__ float t[32][33];
    int bxi = blockIdx.x;
    const float* W;
    __half* dst;
    int N;
    float scale;
    if (bxi < 64) {
        W = Wq; dst = Wt; N = 2048; scale = sc;
    } else if (bxi < 80) {
        W = Wk; dst = Wt + (size_t)2048 * 2048; N = 512; scale = 1.f;
        bxi -= 64;
    } else {
        W = Wv; dst = Wt + (size_t)2560 * 2048; N = 512; scale = 1.f;
        bxi -= 80;
    }
    const int bx = bxi * 32;
    const int by = blockIdx.y * 32;
    const int x = threadIdx.x;
    const int y = threadIdx.y;
#pragma unroll
    for (int i = 0; i < 32; i += 8)
        t[y + i][x] = W[(size_t)(by + y + i) * N + bx + x];
    __syncthreads();
#pragma unroll
    for (int i = 0; i < 32; i += 8)
        dst[(size_t)(bx + y + i) * 2048 + by + x] =
            __float2half_rn(t[x][y + i] * scale);
}

// ============================ fp16 GEMM ============================
// QKV[4096][3072] = xh[4096,2048] @ Wth[3072,2048]^T.
// Tile 128(m) x 256(n) x 32(k), 8 warps (warp tile 64x64), 3-stage cp.async.
#define GNCH (D_MODEL / 32)
#define GTA 10240u   // A stage bytes: 128 rows * 80B
#define GTBB 20480u  // B stage bytes: 256 rows * 80B
#define GS_B 30720u  // B base (after 3 A stages)
#define SMEM_GEMM (GS_B + 3 * GTBB)   // 92160

__global__ __launch_bounds__(256, 1) void gemm_h3(
    const __half* __restrict__ A, const __half* __restrict__ Bt,
    __half* __restrict__ C) {
    extern __shared__ __half dsm[];
    const uint32_t s0 = smem_u32(dsm);

    const int tid = threadIdx.x;
    const int lane = tid & 31;
    const int warp = tid >> 5;
    const int wm = warp & 1;
    const int wn = warp >> 1;
    const int m0 = blockIdx.y * 128;
    const int n0 = blockIdx.x * 256;
    const int grp = lane >> 2;
    const int tk = lane & 3;
    const int l15 = lane & 15;
    const int lhi = lane >> 4;
    const int cr = tid >> 2;
    const int cq = tid & 3;

    const char* Ag = (const char*)(A + (size_t)m0 * D_MODEL);
    const char* Bg = (const char*)(Bt + (size_t)n0 * D_MODEL);

    float acc[4][8][4];
#pragma unroll
    for (int i = 0; i < 4; i++)
#pragma unroll
        for (int j = 0; j < 8; j++)
#pragma unroll
            for (int v = 0; v < 4; v++) acc[i][j][v] = 0.f;

#pragma unroll
    for (int s = 0; s < 2; s++) {
#pragma unroll
        for (int i = 0; i < 2; i++) {
            int r = i * 64 + cr;
            CP16(s0 + s * GTA + r * 80 + cq * 16,
                 Ag + (size_t)r * 4096 + s * 64 + cq * 16);
        }
#pragma unroll
        for (int i = 0; i < 4; i++) {
            int r = i * 64 + cr;
            CP16(s0 + GS_B + s * GTBB + r * 80 + cq * 16,
                 Bg + (size_t)r * 4096 + s * 64 + cq * 16);
        }
        CP_COMMIT();
    }

    for (int c = 0; c < GNCH; c++) {
        if (c + 1 < GNCH) { CP_WAIT1(); } else { CP_WAIT0(); }
        __syncthreads();

        if (c + 2 < GNCH) {
            const int st = (c + 2) % 3;
            const size_t ko = (size_t)(c + 2) * 64;
#pragma unroll
            for (int i = 0; i < 2; i++) {
                int r = i * 64 + cr;
                CP16(s0 + st * GTA + r * 80 + cq * 16,
                     Ag + (size_t)r * 4096 + ko + cq * 16);
            }
#pragma unroll
            for (int i = 0; i < 4; i++) {
                int r = i * 64 + cr;
                CP16(s0 + GS_B + st * GTBB + r * 80 + cq * 16,
                     Bg + (size_t)r * 4096 + ko + cq * 16);
            }
            CP_COMMIT();
        }

        const uint32_t ab = s0 + (c % 3) * GTA;
        const uint32_t bb = s0 + GS_B + (c % 3) * GTBB;
#pragma unroll
        for (int ks = 0; ks < 2; ks++) {
            uint32_t a[4][4], bq[4][4];
#pragma unroll
            for (int mf = 0; mf < 4; mf++)
                ldm_x4(a[mf], ab + (wm * 64 + mf * 16 + l15) * 80 + lhi * 16 +
                                  ks * 32);
#pragma unroll
            for (int nh = 0; nh < 4; nh++)
                ldm_x4(bq[nh], bb + (wn * 64 + nh * 16 + l15) * 80 +
                                   lhi * 16 + ks * 32);
#pragma unroll
            for (int mf = 0; mf < 4; mf++)
#pragma unroll
                for (int nf = 0; nf < 8; nf++) {
                    uint32_t b2[2] = {bq[nf >> 1][nf & 1],
                                      bq[nf >> 1][2 + (nf & 1)]};
                    mma_f16(acc[mf][nf], a[mf], b2);
                }
        }
    }

#pragma unroll
    for (int mf = 0; mf < 4; mf++) {
#pragma unroll
        for (int nf = 0; nf < 8; nf++) {
            int r = m0 + wm * 64 + mf * 16 + grp;
            int cc = n0 + wn * 64 + nf * 8 + 2 * tk;
            *reinterpret_cast<__half2*>(C + (size_t)r * QKVW + cc) =
                __floats2half2_rn(acc[mf][nf][0], acc[mf][nf][1]);
            *reinterpret_cast<__half2*>(C + (size_t)(r + 8) * QKVW + cc) =
                __floats2half2_rn(acc[mf][nf][2], acc[mf][nf][3]);
        }
    }
}

// ============================ fp16 attention ============================
// 256 threads (8 warps), 256-query tile, warp m-tile 32 rows (2 m-frags):
// K/V fragments loaded ONCE per tile feed both m-frags (LDSM amortized 2x).
// Register-resident P; l via constant all-ones B-fragment MMA.
#define ATS 9216u                 // bytes per K (or V) stage
#define AVB (3 * ATS)             // V base  (27648)
#define SMEM_ATTN (6 * ATS)       // 55296

__global__ __launch_bounds__(256) void attn_h(
    const __half* __restrict__ QKV, float* __restrict__ out) {
    extern __shared__ __half dsm[];
    const uint32_t s0 = smem_u32(dsm);

    const int qt = gridDim.x - 1 - blockIdx.x;  // longest blocks first
    const int h = blockIdx.y;
    const int b = blockIdx.z;
    const int kvh = h >> 2;
    const int tid = threadIdx.x;
    const int lane = tid & 31;
    const int w = tid >> 5;
    const int grp = lane >> 2;
    const int tk = lane & 3;
    const int l15 = lane & 15;
    const int lhi = lane >> 4;
    const int q0 = qt * 256;
    const int rbase = 32 * w + grp;      // warp rows: rbase + {0,8,16,24}

    // Q fragments for both 16-row m-halves.
    uint32_t qf[2][4][4];
#pragma unroll
    for (int mh = 0; mh < 2; mh++) {
        const __half* qb0 =
            QKV + ((size_t)(b * T_) + q0 + rbase + 16 * mh) * QKVW + h * HD;
        const __half* qb1 = qb0 + 8 * QKVW;
#pragma unroll
        for (int ks = 0; ks < 4; ks++) {
            qf[mh][ks][0] = *(const uint32_t*)(qb0 + 16 * ks + 2 * tk);
            qf[mh][ks][1] = *(const uint32_t*)(qb1 + 16 * ks + 2 * tk);
            qf[mh][ks][2] = *(const uint32_t*)(qb0 + 16 * ks + 2 * tk + 8);
            qf[mh][ks][3] = *(const uint32_t*)(qb1 + 16 * ks + 2 * tk + 8);
        }
    }

    // of[mh][0..7]: O accumulators; of[mh][8]: l accumulator.
    float of[2][9][4];
#pragma unroll
    for (int mh = 0; mh < 2; mh++)
#pragma unroll
        for (int nf = 0; nf < 9; nf++)
#pragma unroll
            for (int v = 0; v < 4; v++) of[mh][nf][v] = 0.f;

    const char* kg =
        (const char*)(QKV + (size_t)(b * T_) * QKVW + 2048 + kvh * HD);
    const char* vg =
        (const char*)(QKV + (size_t)(b * T_) * QKVW + 2560 + kvh * HD);
    const int crow = tid >> 3;   // 0..31 (+32 second pass)
    const int cq8 = tid & 7;
    const int jend = 4 * qt + 3;

    // Prologue: tiles 0 and 1 into stages 0, 1.
#pragma unroll
    for (int s = 0; s < 2; s++) {
        const size_t go = (size_t)s * 64 * 6144;
#pragma unroll
        for (int i = 0; i < 2; i++) {
            int rr = i * 32 + crow;
            CP16(s0 + s * ATS + rr * 144 + cq8 * 16,
                 kg + (size_t)rr * 6144 + go + cq8 * 16);
            CP16(s0 + AVB + s * ATS + rr * 144 + cq8 * 16,
                 vg + (size_t)rr * 6144 + go + cq8 * 16);
        }
        CP_COMMIT();
    }

    const uint32_t ONES2[2] = {0x3C003C00u, 0x3C003C00u};  // half2(1,1) x2

    for (int jt = 0; jt <= jend; jt++) {
        if (jt < jend) { CP_WAIT1(); } else { CP_WAIT0(); }
        __syncthreads();

        if (jt + 2 <= jend) {
            const int st = (jt + 2) % 3;
            const size_t go = (size_t)(jt + 2) * 64 * 6144;
#pragma unroll
            for (int i = 0; i < 2; i++) {
                int rr = i * 32 + crow;
                CP16(s0 + st * ATS + rr * 144 + cq8 * 16,
                     kg + (size_t)rr * 6144 + go + cq8 * 16);
                CP16(s0 + AVB + st * ATS + rr * 144 + cq8 * 16,
                     vg + (size_t)rr * 6144 + go + cq8 * 16);
            }
            CP_COMMIT();
        }

        // Skip warps whose entire 32-row range is masked by causality.
        const bool active = (jt * 64) <= (q0 + 32 * w + 31);
        if (active) {
            const uint32_t kb = s0 + (jt % 3) * ATS;
            const uint32_t vb = s0 + AVB + (jt % 3) * ATS;

            // S = Q K^T for both m-halves; K fragments loaded once.
            float sa[2][8][4];
#pragma unroll
            for (int mh = 0; mh < 2; mh++)
#pragma unroll
                for (int nf = 0; nf < 8; nf++)
#pragma unroll
                    for (int v = 0; v < 4; v++) sa[mh][nf][v] = 0.f;
#pragma unroll
            for (int ks = 0; ks < 4; ks++) {
                uint32_t kq[4][4];
#pragma unroll
                for (int nh = 0; nh < 4; nh++)
                    ldm_x4(kq[nh],
                           kb + (nh * 16 + l15) * 144 + lhi * 16 + ks * 32);
#pragma unroll
                for (int nf = 0; nf < 8; nf++) {
                    uint32_t b2[2] = {kq[nf >> 1][nf & 1],
                                      kq[nf >> 1][2 + (nf & 1)]};
                    mma_f16(sa[0][nf], qf[0][ks], b2);
                    mma_f16(sa[1][nf], qf[1][ks], b2);
                }
            }

            if (jt >= 4 * qt) {
                const int colb = jt * 64;
#pragma unroll
                for (int mh = 0; mh < 2; mh++) {
                    const int rg0 = q0 + rbase + 16 * mh;
                    const int rg1 = rg0 + 8;
#pragma unroll
                    for (int nf = 0; nf < 8; nf++) {
                        int c0 = colb + 8 * nf + 2 * tk;
                        if (c0 > rg0) sa[mh][nf][0] = -1e30f;
                        if (c0 + 1 > rg0) sa[mh][nf][1] = -1e30f;
                        if (c0 > rg1) sa[mh][nf][2] = -1e30f;
                        if (c0 + 1 > rg1) sa[mh][nf][3] = -1e30f;
                    }
                }
            }

            // P = exp2(S) -> PV A-fragments (register resident).
            uint32_t pm[2][4][4];
#pragma unroll
            for (int mh = 0; mh < 2; mh++)
#pragma unroll
                for (int nf = 0; nf < 8; nf++) {
                    __half2 a01 =
                        __floats2half2_rn(sa[mh][nf][0], sa[mh][nf][1]);
                    __half2 a23 =
                        __floats2half2_rn(sa[mh][nf][2], sa[mh][nf][3]);
                    pm[mh][nf >> 1][(nf & 1) * 2] =
                        h2ex2(*reinterpret_cast<uint32_t*>(&a01));
                    pm[mh][nf >> 1][(nf & 1) * 2 + 1] =
                        h2ex2(*reinterpret_cast<uint32_t*>(&a23));
                }

            // O += P V ; l += P @ ones. V fragments loaded once per ks.
#pragma unroll
            for (int ks = 0; ks < 4; ks++) {
                uint32_t vq[4][4];
#pragma unroll
                for (int dh = 0; dh < 4; dh++)
                    ldm_x4t(vq[dh],
                            vb + (ks * 16 + l15) * 144 + lhi * 16 + dh * 32);
#pragma unroll
                for (int nf = 0; nf < 8; nf++) {
                    uint32_t b2[2] = {vq[nf >> 1][2 * (nf & 1)],
                                      vq[nf >> 1][2 * (nf & 1) + 1]};
                    mma_f16(of[0][nf], pm[0][ks], b2);
                    mma_f16(of[1][nf], pm[1][ks], b2);
                }
                mma_f16(of[0][8], pm[0][ks], ONES2);
                mma_f16(of[1][8], pm[1][ks], ONES2);
            }
        }
    }

    // Epilogue per m-half.
#pragma unroll
    for (int mh = 0; mh < 2; mh++) {
        const float l0 = __shfl_sync(0xffffffffu, of[mh][8][0], lane & ~3);
        const float l1 = __shfl_sync(0xffffffffu, of[mh][8][2], lane & ~3);
        const float inv0 = 1.f / l0;
        const float inv1 = 1.f / l1;
        float* g0 = out +
            ((size_t)(b * T_) + q0 + rbase + 16 * mh) * (NQ * HD) + h * HD;
        float* g1 = g0 + 8 * (NQ * HD);
#pragma unroll
        for (int nf = 0; nf < 8; nf++) {
            int c = 8 * nf + 2 * tk;
            *reinterpret_cast<float2*>(g0 + c) =
                make_float2(of[mh][nf][0] * inv0, of[mh][nf][1] * inv0);
            *reinterpret_cast<float2*>(g1 + c) =
                make_float2(of[mh][nf][2] * inv1, of[mh][nf][3] * inv1);
        }
    }
}

// ============================ Launch ============================
extern "C" void kernel_launch(void* const* d_in, const int* in_sizes, int n_in,
                              void* d_out, int out_size) {
    (void)in_sizes; (void)n_in; (void)out_size;
    const float* x = (const float*)d_in[0];
    const float* Wq = (const float*)d_in[1];
    const float* Wk = (const float*)d_in[2];
    const float* Wv = (const float*)d_in[3];
    float* out = (float*)d_out;

    __half *xh, *QKVh, *Wth;
    cudaGetSymbolAddress((void**)&xh, g_xh);
    cudaGetSymbolAddress((void**)&QKVh, g_QKVh);
    cudaGetSymbolAddress((void**)&Wth, g_Wth);

    const float sc = 0.125f * 1.4426950408889634f;

    cvt_x<<<(ROWS * D_MODEL) / (256 * 4), 256>>>(x, xh);
    transpose_all<<<dim3(96, 64), dim3(32, 8)>>>(Wq, Wk, Wv, Wth, sc);

    cudaFuncSetAttribute(gemm_h3, cudaFuncAttributeMaxDynamicSharedMemorySize,
                         SMEM_GEMM);
    gemm_h3<<<dim3(QKVW / 256, ROWS / 128), 256, SMEM_GEMM>>>(xh, Wth, QKVh);

    cudaFuncSetAttribute(attn_h, cudaFuncAttributeMaxDynamicSharedMemorySize,
                         SMEM_ATTN);
    dim3 ga(T_ / 256, NQ, B_);
    attn_h<<<ga, 256, SMEM_ATTN>>>(QKVh, out);
}

// round 16
// speedup vs baseline: 1.0451x; 1.0451x over previous
#include <cuda_runtime.h>
#include <cuda_fp16.h>
#include <math.h>
#include <stdint.h>

#define D_MODEL 2048
#define NQ 32
#define NKV 8
#define HD 64
#define B_ 2
#define T_ 2048
#define ROWS (B_ * T_)
#define QKVW 3072   // Q | K | V packed row width

// Scratch (allocation-free device globals), all fp16.
__device__ __half g_xh[(size_t)ROWS * D_MODEL];        // x in half
__device__ __half g_QKVh[(size_t)ROWS * QKVW];         // Q|K|V packed
__device__ __half g_Wth[(size_t)QKVW * D_MODEL];       // Wq^T|Wk^T|Wv^T

// ============================ PTX helpers ============================
__device__ __forceinline__ uint32_t smem_u32(const void* p) {
    uint32_t a;
    asm("{ .reg .u64 t; cvta.to.shared.u64 t, %1; cvt.u32.u64 %0, t; }"
        : "=r"(a) : "l"(p));
    return a;
}
__device__ __forceinline__ uint32_t h2ex2(uint32_t x) {
    uint32_t y;
    asm("ex2.approx.f16x2 %0, %1;" : "=r"(y) : "r"(x));
    return y;
}
#define CP16(dst, src) \
    asm volatile("cp.async.cg.shared.global [%0], [%1], 16;" \
                 :: "r"(dst), "l"(src))
#define CP_COMMIT() asm volatile("cp.async.commit_group;" ::: "memory")
#define CP_WAIT0() asm volatile("cp.async.wait_group 0;" ::: "memory")
#define CP_WAIT1() asm volatile("cp.async.wait_group 1;" ::: "memory")

__device__ __forceinline__ void ldm_x4(uint32_t* r, uint32_t a) {
    asm volatile("ldmatrix.sync.aligned.m8n8.x4.shared.b16 {%0,%1,%2,%3}, [%4];"
                 : "=r"(r[0]), "=r"(r[1]), "=r"(r[2]), "=r"(r[3]) : "r"(a));
}
__device__ __forceinline__ void ldm_x4t(uint32_t* r, uint32_t a) {
    asm volatile(
        "ldmatrix.sync.aligned.m8n8.x4.trans.shared.b16 {%0,%1,%2,%3}, [%4];"
        : "=r"(r[0]), "=r"(r[1]), "=r"(r[2]), "=r"(r[3]) : "r"(a));
}
__device__ __forceinline__ void mma_f16(float* d, const uint32_t* a,
                                        const uint32_t* b) {
    asm volatile(
        "mma.sync.aligned.m16n8k16.row.col.f32.f16.f16.f32 "
        "{%0,%1,%2,%3}, {%4,%5,%6,%7}, {%8,%9}, {%0,%1,%2,%3};"
        : "+f"(d[0]), "+f"(d[1]), "+f"(d[2]), "+f"(d[3])
        : "r"(a[0]), "r"(a[1]), "r"(a[2]), "r"(a[3]), "r"(b[0]), "r"(b[1]));
}

// ============================ x -> half ============================
__global__ __launch_bounds__(256) void cvt_x(const float* __restrict__ x,
                                             __half* __restrict__ xh) {
    int i = (blockIdx.x * 256 + threadIdx.x) * 4;
    float4 v = *reinterpret_cast<const float4*>(x + i);
    *reinterpret_cast<__half2*>(xh + i) = __floats2half2_rn(v.x, v.y);
    *reinterpret_cast<__half2*>(xh + i + 2) = __floats2half2_rn(v.z, v.w);
}

// ============================ W transposes (one launch) ============================
__global__ __launch_bounds__(256) void transpose_all(
    const float* __restrict__ Wq, const float* __restrict__ Wk,
    const float* __restrict__ Wv, __half* __restrict__ Wt, float sc) {
    __shared__ float t[32][33];
    int bxi = blockIdx.x;
    const float* W;
    __half* dst;
    int N;
    float scale;
    if (bxi < 64) {
        W = Wq; dst = Wt; N = 2048; scale = sc;
    } else if (bxi < 80) {
        W = Wk; dst = Wt + (size_t)2048 * 2048; N = 512; scale = 1.f;
        bxi -= 64;
    } else {
        W = Wv; dst = Wt + (size_t)2560 * 2048; N = 512; scale = 1.f;
        bxi -= 80;
    }
    const int bx = bxi * 32;
    const int by = blockIdx.y * 32;
    const int x = threadIdx.x;
    const int y = threadIdx.y;
#pragma unroll
    for (int i = 0; i < 32; i += 8)
        t[y + i][x] = W[(size_t)(by + y + i) * N + bx + x];
    __syncthreads();
#pragma unroll
    for (int i = 0; i < 32; i += 8)
        dst[(size_t)(bx + y + i) * 2048 + by + x] =
            __float2half_rn(t[x][y + i] * scale);
}

// ============================ fp16 GEMM ============================
// QKV[4096][3072] = xh[4096,2048] @ Wth[3072,2048]^T.
// Tile 128(m) x 256(n) x 32(k), 8 warps (warp tile 64x64), 3-stage cp.async.
#define GNCH (D_MODEL / 32)
#define GTA 10240u   // A stage bytes: 128 rows * 80B
#define GTBB 20480u  // B stage bytes: 256 rows * 80B
#define GS_B 30720u  // B base (after 3 A stages)
#define SMEM_GEMM (GS_B + 3 * GTBB)   // 92160

__global__ __launch_bounds__(256, 1) void gemm_h3(
    const __half* __restrict__ A, const __half* __restrict__ Bt,
    __half* __restrict__ C) {
    extern __shared__ __half dsm[];
    const uint32_t s0 = smem_u32(dsm);

    const int tid = threadIdx.x;
    const int lane = tid & 31;
    const int warp = tid >> 5;
    const int wm = warp & 1;
    const int wn = warp >> 1;
    const int m0 = blockIdx.y * 128;
    const int n0 = blockIdx.x * 256;
    const int grp = lane >> 2;
    const int tk = lane & 3;
    const int l15 = lane & 15;
    const int lhi = lane >> 4;
    const int cr = tid >> 2;
    const int cq = tid & 3;

    const char* Ag = (const char*)(A + (size_t)m0 * D_MODEL);
    const char* Bg = (const char*)(Bt + (size_t)n0 * D_MODEL);

    float acc[4][8][4];
#pragma unroll
    for (int i = 0; i < 4; i++)
#pragma unroll
        for (int j = 0; j < 8; j++)
#pragma unroll
            for (int v = 0; v < 4; v++) acc[i][j][v] = 0.f;

#pragma unroll
    for (int s = 0; s < 2; s++) {
#pragma unroll
        for (int i = 0; i < 2; i++) {
            int r = i * 64 + cr;
            CP16(s0 + s * GTA + r * 80 + cq * 16,
                 Ag + (size_t)r * 4096 + s * 64 + cq * 16);
        }
#pragma unroll
        for (int i = 0; i < 4; i++) {
            int r = i * 64 + cr;
            CP16(s0 + GS_B + s * GTBB + r * 80 + cq * 16,
                 Bg + (size_t)r * 4096 + s * 64 + cq * 16);
        }
        CP_COMMIT();
    }

    for (int c = 0; c < GNCH; c++) {
        if (c + 1 < GNCH) { CP_WAIT1(); } else { CP_WAIT0(); }
        __syncthreads();

        if (c + 2 < GNCH) {
            const int st = (c + 2) % 3;
            const size_t ko = (size_t)(c + 2) * 64;
#pragma unroll
            for (int i = 0; i < 2; i++) {
                int r = i * 64 + cr;
                CP16(s0 + st * GTA + r * 80 + cq * 16,
                     Ag + (size_t)r * 4096 + ko + cq * 16);
            }
#pragma unroll
            for (int i = 0; i < 4; i++) {
                int r = i * 64 + cr;
                CP16(s0 + GS_B + st * GTBB + r * 80 + cq * 16,
                     Bg + (size_t)r * 4096 + ko + cq * 16);
            }
            CP_COMMIT();
        }

        const uint32_t ab = s0 + (c % 3) * GTA;
        const uint32_t bb = s0 + GS_B + (c % 3) * GTBB;
#pragma unroll
        for (int ks = 0; ks < 2; ks++) {
            uint32_t a[4][4], bq[4][4];
#pragma unroll
            for (int mf = 0; mf < 4; mf++)
                ldm_x4(a[mf], ab + (wm * 64 + mf * 16 + l15) * 80 + lhi * 16 +
                                  ks * 32);
#pragma unroll
            for (int nh = 0; nh < 4; nh++)
                ldm_x4(bq[nh], bb + (wn * 64 + nh * 16 + l15) * 80 +
                                   lhi * 16 + ks * 32);
#pragma unroll
            for (int mf = 0; mf < 4; mf++)
#pragma unroll
                for (int nf = 0; nf < 8; nf++) {
                    uint32_t b2[2] = {bq[nf >> 1][nf & 1],
                                      bq[nf >> 1][2 + (nf & 1)]};
                    mma_f16(acc[mf][nf], a[mf], b2);
                }
        }
    }

#pragma unroll
    for (int mf = 0; mf < 4; mf++) {
#pragma unroll
        for (int nf = 0; nf < 8; nf++) {
            int r = m0 + wm * 64 + mf * 16 + grp;
            int cc = n0 + wn * 64 + nf * 8 + 2 * tk;
            *reinterpret_cast<__half2*>(C + (size_t)r * QKVW + cc) =
                __floats2half2_rn(acc[mf][nf][0], acc[mf][nf][1]);
            *reinterpret_cast<__half2*>(C + (size_t)(r + 8) * QKVW + cc) =
                __floats2half2_rn(acc[mf][nf][2], acc[mf][nf][3]);
        }
    }
}

// ============================ fp16 attention ============================
// 128 threads (4 warps), 128-query tile, warp m-tile 32 rows (2 m-frags):
// K/V fragments loaded once per tile feed both m-frags (LDSM amortized 2x),
// packaged as 4-warp blocks so 2 blocks/SM co-schedule (barrier overlap).
// Register-resident P; l via constant all-ones B-fragment MMA.
#define ATS 9216u                 // bytes per K (or V) stage
#define AVB (3 * ATS)             // V base  (27648)
#define SMEM_ATTN (6 * ATS)       // 55296

__global__ __launch_bounds__(128, 2) void attn_h(
    const __half* __restrict__ QKV, float* __restrict__ out) {
    extern __shared__ __half dsm[];
    const uint32_t s0 = smem_u32(dsm);

    const int qt = gridDim.x - 1 - blockIdx.x;  // longest blocks first
    const int h = blockIdx.y;
    const int b = blockIdx.z;
    const int kvh = h >> 2;
    const int tid = threadIdx.x;
    const int lane = tid & 31;
    const int w = tid >> 5;              // 0..3
    const int grp = lane >> 2;
    const int tk = lane & 3;
    const int l15 = lane & 15;
    const int lhi = lane >> 4;
    const int q0 = qt * 128;
    const int rbase = 32 * w + grp;      // warp rows: rbase + {0,8,16,24}

    // Q fragments for both 16-row m-halves.
    uint32_t qf[2][4][4];
#pragma unroll
    for (int mh = 0; mh < 2; mh++) {
        const __half* qb0 =
            QKV + ((size_t)(b * T_) + q0 + rbase + 16 * mh) * QKVW + h * HD;
        const __half* qb1 = qb0 + 8 * QKVW;
#pragma unroll
        for (int ks = 0; ks < 4; ks++) {
            qf[mh][ks][0] = *(const uint32_t*)(qb0 + 16 * ks + 2 * tk);
            qf[mh][ks][1] = *(const uint32_t*)(qb1 + 16 * ks + 2 * tk);
            qf[mh][ks][2] = *(const uint32_t*)(qb0 + 16 * ks + 2 * tk + 8);
            qf[mh][ks][3] = *(const uint32_t*)(qb1 + 16 * ks + 2 * tk + 8);
        }
    }

    // of[mh][0..7]: O accumulators; of[mh][8]: l accumulator.
    float of[2][9][4];
#pragma unroll
    for (int mh = 0; mh < 2; mh++)
#pragma unroll
        for (int nf = 0; nf < 9; nf++)
#pragma unroll
            for (int v = 0; v < 4; v++) of[mh][nf][v] = 0.f;

    const char* kg =
        (const char*)(QKV + (size_t)(b * T_) * QKVW + 2048 + kvh * HD);
    const char* vg =
        (const char*)(QKV + (size_t)(b * T_) * QKVW + 2560 + kvh * HD);
    const int crow = tid >> 3;   // 0..15 (+16/32/48 passes)
    const int cq8 = tid & 7;
    const int jend = 2 * qt + 1;

    // Prologue: tiles 0 and 1 into stages 0, 1.
#pragma unroll
    for (int s = 0; s < 2; s++) {
        const size_t go = (size_t)s * 64 * 6144;
#pragma unroll
        for (int i = 0; i < 4; i++) {
            int rr = i * 16 + crow;
            CP16(s0 + s * ATS + rr * 144 + cq8 * 16,
                 kg + (size_t)rr * 6144 + go + cq8 * 16);
            CP16(s0 + AVB + s * ATS + rr * 144 + cq8 * 16,
                 vg + (size_t)rr * 6144 + go + cq8 * 16);
        }
        CP_COMMIT();
    }

    const uint32_t ONES2[2] = {0x3C003C00u, 0x3C003C00u};  // half2(1,1) x2

    for (int jt = 0; jt <= jend; jt++) {
        if (jt < jend) { CP_WAIT1(); } else { CP_WAIT0(); }
        __syncthreads();

        if (jt + 2 <= jend) {
            const int st = (jt + 2) % 3;
            const size_t go = (size_t)(jt + 2) * 64 * 6144;
#pragma unroll
            for (int i = 0; i < 4; i++) {
                int rr = i * 16 + crow;
                CP16(s0 + st * ATS + rr * 144 + cq8 * 16,
                     kg + (size_t)rr * 6144 + go + cq8 * 16);
                CP16(s0 + AVB + st * ATS + rr * 144 + cq8 * 16,
                     vg + (size_t)rr * 6144 + go + cq8 * 16);
            }
            CP_COMMIT();
        }

        // Skip warps whose entire 32-row range is masked by causality.
        const bool active = (jt * 64) <= (q0 + 32 * w + 31);
        if (active) {
            const uint32_t kb = s0 + (jt % 3) * ATS;
            const uint32_t vb = s0 + AVB + (jt % 3) * ATS;

            // S = Q K^T for both m-halves; K fragments loaded once.
            float sa[2][8][4];
#pragma unroll
            for (int mh = 0; mh < 2; mh++)
#pragma unroll
                for (int nf = 0; nf < 8; nf++)
#pragma unroll
                    for (int v = 0; v < 4; v++) sa[mh][nf][v] = 0.f;
#pragma unroll
            for (int ks = 0; ks < 4; ks++) {
                uint32_t kq[4][4];
#pragma unroll
                for (int nh = 0; nh < 4; nh++)
                    ldm_x4(kq[nh],
                           kb + (nh * 16 + l15) * 144 + lhi * 16 + ks * 32);
#pragma unroll
                for (int nf = 0; nf < 8; nf++) {
                    uint32_t b2[2] = {kq[nf >> 1][nf & 1],
                                      kq[nf >> 1][2 + (nf & 1)]};
                    mma_f16(sa[0][nf], qf[0][ks], b2);
                    mma_f16(sa[1][nf], qf[1][ks], b2);
                }
            }

            if (jt >= 2 * qt) {
                const int colb = jt * 64;
#pragma unroll
                for (int mh = 0; mh < 2; mh++) {
                    const int rg0 = q0 + rbase + 16 * mh;
                    const int rg1 = rg0 + 8;
#pragma unroll
                    for (int nf = 0; nf < 8; nf++) {
                        int c0 = colb + 8 * nf + 2 * tk;
                        if (c0 > rg0) sa[mh][nf][0] = -1e30f;
                        if (c0 + 1 > rg0) sa[mh][nf][1] = -1e30f;
                        if (c0 > rg1) sa[mh][nf][2] = -1e30f;
                        if (c0 + 1 > rg1) sa[mh][nf][3] = -1e30f;
                    }
                }
            }

            // P = exp2(S) -> PV A-fragments (register resident).
            uint32_t pm[2][4][4];
#pragma unroll
            for (int mh = 0; mh < 2; mh++)
#pragma unroll
                for (int nf = 0; nf < 8; nf++) {
                    __half2 a01 =
                        __floats2half2_rn(sa[mh][nf][0], sa[mh][nf][1]);
                    __half2 a23 =
                        __floats2half2_rn(sa[mh][nf][2], sa[mh][nf][3]);
                    pm[mh][nf >> 1][(nf & 1) * 2] =
                        h2ex2(*reinterpret_cast<uint32_t*>(&a01));
                    pm[mh][nf >> 1][(nf & 1) * 2 + 1] =
                        h2ex2(*reinterpret_cast<uint32_t*>(&a23));
                }

            // O += P V ; l += P @ ones. V fragments loaded once per ks.
#pragma unroll
            for (int ks = 0; ks < 4; ks++) {
                uint32_t vq[4][4];
#pragma unroll
                for (int dh = 0; dh < 4; dh++)
                    ldm_x4t(vq[dh],
                            vb + (ks * 16 + l15) * 144 + lhi * 16 + dh * 32);
#pragma unroll
                for (int nf = 0; nf < 8; nf++) {
                    uint32_t b2[2] = {vq[nf >> 1][2 * (nf & 1)],
                                      vq[nf >> 1][2 * (nf & 1) + 1]};
                    mma_f16(of[0][nf], pm[0][ks], b2);
                    mma_f16(of[1][nf], pm[1][ks], b2);
                }
                mma_f16(of[0][8], pm[0][ks], ONES2);
                mma_f16(of[1][8], pm[1][ks], ONES2);
            }
        }
    }

    // Epilogue per m-half.
#pragma unroll
    for (int mh = 0; mh < 2; mh++) {
        const float l0 = __shfl_sync(0xffffffffu, of[mh][8][0], lane & ~3);
        const float l1 = __shfl_sync(0xffffffffu, of[mh][8][2], lane & ~3);
        const float inv0 = 1.f / l0;
        const float inv1 = 1.f / l1;
        float* g0 = out +
            ((size_t)(b * T_) + q0 + rbase + 16 * mh) * (NQ * HD) + h * HD;
        float* g1 = g0 + 8 * (NQ * HD);
#pragma unroll
        for (int nf = 0; nf < 8; nf++) {
            int c = 8 * nf + 2 * tk;
            *reinterpret_cast<float2*>(g0 + c) =
                make_float2(of[mh][nf][0] * inv0, of[mh][nf][1] * inv0);
            *reinterpret_cast<float2*>(g1 + c) =
                make_float2(of[mh][nf][2] * inv1, of[mh][nf][3] * inv1);
        }
    }
}

// ============================ Launch ============================
extern "C" void kernel_launch(void* const* d_in, const int* in_sizes, int n_in,
                              void* d_out, int out_size) {
    (void)in_sizes; (void)n_in; (void)out_size;
    const float* x = (const float*)d_in[0];
    const float* Wq = (const float*)d_in[1];
    const float* Wk = (const float*)d_in[2];
    const float* Wv = (const float*)d_in[3];
    float* out = (float*)d_out;

    __half *xh, *QKVh, *Wth;
    cudaGetSymbolAddress((void**)&xh, g_xh);
    cudaGetSymbolAddress((void**)&QKVh, g_QKVh);
    cudaGetSymbolAddress((void**)&Wth, g_Wth);

    const float sc = 0.125f * 1.4426950408889634f;

    cvt_x<<<(ROWS * D_MODEL) / (256 * 4), 256>>>(x, xh);
    transpose_all<<<dim3(96, 64), dim3(32, 8)>>>(Wq, Wk, Wv, Wth, sc);

    cudaFuncSetAttribute(gemm_h3, cudaFuncAttributeMaxDynamicSharedMemorySize,
                         SMEM_GEMM);
    gemm_h3<<<dim3(QKVW / 256, ROWS / 128), 256, SMEM_GEMM>>>(xh, Wth, QKVh);

    cudaFuncSetAttribute(attn_h, cudaFuncAttributeMaxDynamicSharedMemorySize,
                         SMEM_ATTN);
    dim3 ga(T_ / 128, NQ, B_);
    attn_h<<<ga, 128, SMEM_ATTN>>>(QKVh, out);
}

// round 17
// speedup vs baseline: 1.0479x; 1.0027x over previous
#include <cuda_runtime.h>
#include <cuda_fp16.h>
#include <math.h>
#include <stdint.h>

#define D_MODEL 2048
#define NQ 32
#define NKV 8
#define HD 64
#define B_ 2
#define T_ 2048
#define ROWS (B_ * T_)
#define QKVW 3072   // Q | K | V packed row width

// Scratch (allocation-free device globals), all fp16.
__device__ __half g_xh[(size_t)ROWS * D_MODEL];        // x in half
__device__ __half g_QKVh[(size_t)ROWS * QKVW];         // Q|K|V packed
__device__ __half g_Wth[(size_t)QKVW * D_MODEL];       // Wq^T|Wk^T|Wv^T

// ============================ PTX helpers ============================
__device__ __forceinline__ uint32_t smem_u32(const void* p) {
    uint32_t a;
    asm("{ .reg .u64 t; cvta.to.shared.u64 t, %1; cvt.u32.u64 %0, t; }"
        : "=r"(a) : "l"(p));
    return a;
}
__device__ __forceinline__ uint32_t h2ex2(uint32_t x) {
    uint32_t y;
    asm("ex2.approx.f16x2 %0, %1;" : "=r"(y) : "r"(x));
    return y;
}
#define CP16(dst, src) \
    asm volatile("cp.async.cg.shared.global [%0], [%1], 16;" \
                 :: "r"(dst), "l"(src))
#define CP_COMMIT() asm volatile("cp.async.commit_group;" ::: "memory")
#define CP_WAIT0() asm volatile("cp.async.wait_group 0;" ::: "memory")
#define CP_WAIT1() asm volatile("cp.async.wait_group 1;" ::: "memory")

__device__ __forceinline__ void ldm_x4(uint32_t* r, uint32_t a) {
    asm volatile("ldmatrix.sync.aligned.m8n8.x4.shared.b16 {%0,%1,%2,%3}, [%4];"
                 : "=r"(r[0]), "=r"(r[1]), "=r"(r[2]), "=r"(r[3]) : "r"(a));
}
__device__ __forceinline__ void ldm_x4t(uint32_t* r, uint32_t a) {
    asm volatile(
        "ldmatrix.sync.aligned.m8n8.x4.trans.shared.b16 {%0,%1,%2,%3}, [%4];"
        : "=r"(r[0]), "=r"(r[1]), "=r"(r[2]), "=r"(r[3]) : "r"(a));
}
__device__ __forceinline__ void mma_f16(float* d, const uint32_t* a,
                                        const uint32_t* b) {
    asm volatile(
        "mma.sync.aligned.m16n8k16.row.col.f32.f16.f16.f32 "
        "{%0,%1,%2,%3}, {%4,%5,%6,%7}, {%8,%9}, {%0,%1,%2,%3};"
        : "+f"(d[0]), "+f"(d[1]), "+f"(d[2]), "+f"(d[3])
        : "r"(a[0]), "r"(a[1]), "r"(a[2]), "r"(a[3]), "r"(b[0]), "r"(b[1]));
}

// ============================ x -> half ============================
__global__ __launch_bounds__(256) void cvt_x(const float* __restrict__ x,
                                             __half* __restrict__ xh) {
    int i = (blockIdx.x * 256 + threadIdx.x) * 4;
    float4 v = *reinterpret_cast<const float4*>(x + i);
    *reinterpret_cast<__half2*>(xh + i) = __floats2half2_rn(v.x, v.y);
    *reinterpret_cast<__half2*>(xh + i + 2) = __floats2half2_rn(v.z, v.w);
}

// ============================ W transposes (one launch) ============================
__global__ __launch_bounds__(256) void transpose_all(
    const float* __restrict__ Wq, const float* __restrict__ Wk,
    const float* __restrict__ Wv, __half* __restrict__ Wt, float sc) {
    __shared__ float t[32][33];
    int bxi = blockIdx.x;
    const float* W;
    __half* dst;
    int N;
    float scale;
    if (bxi < 64) {
        W = Wq; dst = Wt; N = 2048; scale = sc;
    } else if (bxi < 80) {
        W = Wk; dst = Wt + (size_t)2048 * 2048; N = 512; scale = 1.f;
        bxi -= 64;
    } else {
        W = Wv; dst = Wt + (size_t)2560 * 2048; N = 512; scale = 1.f;
        bxi -= 80;
    }
    const int bx = bxi * 32;
    const int by = blockIdx.y * 32;
    const int x = threadIdx.x;
    const int y = threadIdx.y;
#pragma unroll
    for (int i = 0; i < 32; i += 8)
        t[y + i][x] = W[(size_t)(by + y + i) * N + bx + x];
    __syncthreads();
#pragma unroll
    for (int i = 0; i < 32; i += 8)
        dst[(size_t)(bx + y + i) * 2048 + by + x] =
            __float2half_rn(t[x][y + i] * scale);
}

// ============================ fp16 GEMM ============================
// QKV[4096][3072] = xh[4096,2048] @ Wth[3072,2048]^T.
// Tile 128(m) x 128(n) x 32(k), 4 warps (warp tile 64x64), 3-stage cp.async,
// 2 blocks/SM so barrier/wait latency is hidden by the co-resident block.
#define GNCH (D_MODEL / 32)
#define GTA 10240u   // per-stage bytes: 128 rows * 80B (A and B alike)
#define GS_B 30720u  // B base (after 3 A stages)
#define SMEM_GEMM (GS_B + 3 * GTA)   // 61440

__global__ __launch_bounds__(128, 2) void gemm_h3(
    const __half* __restrict__ A, const __half* __restrict__ Bt,
    __half* __restrict__ C) {
    extern __shared__ __half dsm[];
    const uint32_t s0 = smem_u32(dsm);

    const int tid = threadIdx.x;
    const int lane = tid & 31;
    const int warp = tid >> 5;
    const int wm = warp & 1;    // 2 m-halves of 64
    const int wn = warp >> 1;   // 2 n-halves of 64
    const int m0 = blockIdx.y * 128;
    const int n0 = blockIdx.x * 128;
    const int grp = lane >> 2;
    const int tk = lane & 3;
    const int l15 = lane & 15;
    const int lhi = lane >> 4;
    const int cr = tid >> 2;    // copy row 0..31 (+32/64/96)
    const int cq = tid & 3;     // 16B chunk (64B per row-k-chunk)

    const char* Ag = (const char*)(A + (size_t)m0 * D_MODEL);
    const char* Bg = (const char*)(Bt + (size_t)n0 * D_MODEL);

    float acc[4][8][4];
#pragma unroll
    for (int i = 0; i < 4; i++)
#pragma unroll
        for (int j = 0; j < 8; j++)
#pragma unroll
            for (int v = 0; v < 4; v++) acc[i][j][v] = 0.f;

    // Prologue: stages 0, 1.
#pragma unroll
    for (int s = 0; s < 2; s++) {
#pragma unroll
        for (int i = 0; i < 4; i++) {
            int r = i * 32 + cr;
            CP16(s0 + s * GTA + r * 80 + cq * 16,
                 Ag + (size_t)r * 4096 + s * 64 + cq * 16);
            CP16(s0 + GS_B + s * GTA + r * 80 + cq * 16,
                 Bg + (size_t)r * 4096 + s * 64 + cq * 16);
        }
        CP_COMMIT();
    }

    for (int c = 0; c < GNCH; c++) {
        if (c + 1 < GNCH) { CP_WAIT1(); } else { CP_WAIT0(); }
        __syncthreads();

        if (c + 2 < GNCH) {
            const int st = (c + 2) % 3;
            const size_t ko = (size_t)(c + 2) * 64;
#pragma unroll
            for (int i = 0; i < 4; i++) {
                int r = i * 32 + cr;
                CP16(s0 + st * GTA + r * 80 + cq * 16,
                     Ag + (size_t)r * 4096 + ko + cq * 16);
                CP16(s0 + GS_B + st * GTA + r * 80 + cq * 16,
                     Bg + (size_t)r * 4096 + ko + cq * 16);
            }
            CP_COMMIT();
        }

        const uint32_t ab = s0 + (c % 3) * GTA;
        const uint32_t bb = s0 + GS_B + (c % 3) * GTA;
#pragma unroll
        for (int ks = 0; ks < 2; ks++) {
            uint32_t a[4][4], bq[4][4];
#pragma unroll
            for (int mf = 0; mf < 4; mf++)
                ldm_x4(a[mf], ab + (wm * 64 + mf * 16 + l15) * 80 + lhi * 16 +
                                  ks * 32);
#pragma unroll
            for (int nh = 0; nh < 4; nh++)
                ldm_x4(bq[nh], bb + (wn * 64 + nh * 16 + l15) * 80 +
                                   lhi * 16 + ks * 32);
#pragma unroll
            for (int mf = 0; mf < 4; mf++)
#pragma unroll
                for (int nf = 0; nf < 8; nf++) {
                    uint32_t b2[2] = {bq[nf >> 1][nf & 1],
                                      bq[nf >> 1][2 + (nf & 1)]};
                    mma_f16(acc[mf][nf], a[mf], b2);
                }
        }
    }

#pragma unroll
    for (int mf = 0; mf < 4; mf++) {
#pragma unroll
        for (int nf = 0; nf < 8; nf++) {
            int r = m0 + wm * 64 + mf * 16 + grp;
            int cc = n0 + wn * 64 + nf * 8 + 2 * tk;
            *reinterpret_cast<__half2*>(C + (size_t)r * QKVW + cc) =
                __floats2half2_rn(acc[mf][nf][0], acc[mf][nf][1]);
            *reinterpret_cast<__half2*>(C + (size_t)(r + 8) * QKVW + cc) =
                __floats2half2_rn(acc[mf][nf][2], acc[mf][nf][3]);
        }
    }
}

// ============================ fp16 attention ============================
// 128 threads (4 warps), 128-query tile, warp m-tile 32 rows (2 m-frags):
// K/V fragments loaded once per tile feed both m-frags (LDSM amortized 2x),
// packaged as 4-warp blocks so 2 blocks/SM co-schedule (barrier overlap).
// Register-resident P; l via constant all-ones B-fragment MMA.
#define ATS 9216u                 // bytes per K (or V) stage
#define AVB (3 * ATS)             // V base  (27648)
#define SMEM_ATTN (6 * ATS)       // 55296

__global__ __launch_bounds__(128, 2) void attn_h(
    const __half* __restrict__ QKV, float* __restrict__ out) {
    extern __shared__ __half dsm[];
    const uint32_t s0 = smem_u32(dsm);

    const int qt = gridDim.x - 1 - blockIdx.x;  // longest blocks first
    const int h = blockIdx.y;
    const int b = blockIdx.z;
    const int kvh = h >> 2;
    const int tid = threadIdx.x;
    const int lane = tid & 31;
    const int w = tid >> 5;              // 0..3
    const int grp = lane >> 2;
    const int tk = lane & 3;
    const int l15 = lane & 15;
    const int lhi = lane >> 4;
    const int q0 = qt * 128;
    const int rbase = 32 * w + grp;      // warp rows: rbase + {0,8,16,24}

    // Q fragments for both 16-row m-halves.
    uint32_t qf[2][4][4];
#pragma unroll
    for (int mh = 0; mh < 2; mh++) {
        const __half* qb0 =
            QKV + ((size_t)(b * T_) + q0 + rbase + 16 * mh) * QKVW + h * HD;
        const __half* qb1 = qb0 + 8 * QKVW;
#pragma unroll
        for (int ks = 0; ks < 4; ks++) {
            qf[mh][ks][0] = *(const uint32_t*)(qb0 + 16 * ks + 2 * tk);
            qf[mh][ks][1] = *(const uint32_t*)(qb1 + 16 * ks + 2 * tk);
            qf[mh][ks][2] = *(const uint32_t*)(qb0 + 16 * ks + 2 * tk + 8);
            qf[mh][ks][3] = *(const uint32_t*)(qb1 + 16 * ks + 2 * tk + 8);
        }
    }

    // of[mh][0..7]: O accumulators; of[mh][8]: l accumulator.
    float of[2][9][4];
#pragma unroll
    for (int mh = 0; mh < 2; mh++)
#pragma unroll
        for (int nf = 0; nf < 9; nf++)
#pragma unroll
            for (int v = 0; v < 4; v++) of[mh][nf][v] = 0.f;

    const char* kg =
        (const char*)(QKV + (size_t)(b * T_) * QKVW + 2048 + kvh * HD);
    const char* vg =
        (const char*)(QKV + (size_t)(b * T_) * QKVW + 2560 + kvh * HD);
    const int crow = tid >> 3;   // 0..15 (+16/32/48 passes)
    const int cq8 = tid & 7;
    const int jend = 2 * qt + 1;

    // Prologue: tiles 0 and 1 into stages 0, 1.
#pragma unroll
    for (int s = 0; s < 2; s++) {
        const size_t go = (size_t)s * 64 * 6144;
#pragma unroll
        for (int i = 0; i < 4; i++) {
            int rr = i * 16 + crow;
            CP16(s0 + s * ATS + rr * 144 + cq8 * 16,
                 kg + (size_t)rr * 6144 + go + cq8 * 16);
            CP16(s0 + AVB + s * ATS + rr * 144 + cq8 * 16,
                 vg + (size_t)rr * 6144 + go + cq8 * 16);
        }
        CP_COMMIT();
    }

    const uint32_t ONES2[2] = {0x3C003C00u, 0x3C003C00u};  // half2(1,1) x2

    for (int jt = 0; jt <= jend; jt++) {
        if (jt < jend) { CP_WAIT1(); } else { CP_WAIT0(); }
        __syncthreads();

        if (jt + 2 <= jend) {
            const int st = (jt + 2) % 3;
            const size_t go = (size_t)(jt + 2) * 64 * 6144;
#pragma unroll
            for (int i = 0; i < 4; i++) {
                int rr = i * 16 + crow;
                CP16(s0 + st * ATS + rr * 144 + cq8 * 16,
                     kg + (size_t)rr * 6144 + go + cq8 * 16);
                CP16(s0 + AVB + st * ATS + rr * 144 + cq8 * 16,
                     vg + (size_t)rr * 6144 + go + cq8 * 16);
            }
            CP_COMMIT();
        }

        // Skip warps whose entire 32-row range is masked by causality.
        const bool active = (jt * 64) <= (q0 + 32 * w + 31);
        if (active) {
            const uint32_t kb = s0 + (jt % 3) * ATS;
            const uint32_t vb = s0 + AVB + (jt % 3) * ATS;

            // S = Q K^T for both m-halves; K fragments loaded once.
            float sa[2][8][4];
#pragma unroll
            for (int mh = 0; mh < 2; mh++)
#pragma unroll
                for (int nf = 0; nf < 8; nf++)
#pragma unroll
                    for (int v = 0; v < 4; v++) sa[mh][nf][v] = 0.f;
#pragma unroll
            for (int ks = 0; ks < 4; ks++) {
                uint32_t kq[4][4];
#pragma unroll
                for (int nh = 0; nh < 4; nh++)
                    ldm_x4(kq[nh],
                           kb + (nh * 16 + l15) * 144 + lhi * 16 + ks * 32);
#pragma unroll
                for (int nf = 0; nf < 8; nf++) {
                    uint32_t b2[2] = {kq[nf >> 1][nf & 1],
                                      kq[nf >> 1][2 + (nf & 1)]};
                    mma_f16(sa[0][nf], qf[0][ks], b2);
                    mma_f16(sa[1][nf], qf[1][ks], b2);
                }
            }

            if (jt >= 2 * qt) {
                const int colb = jt * 64;
#pragma unroll
                for (int mh = 0; mh < 2; mh++) {
                    const int rg0 = q0 + rbase + 16 * mh;
                    const int rg1 = rg0 + 8;
#pragma unroll
                    for (int nf = 0; nf < 8; nf++) {
                        int c0 = colb + 8 * nf + 2 * tk;
                        if (c0 > rg0) sa[mh][nf][0] = -1e30f;
                        if (c0 + 1 > rg0) sa[mh][nf][1] = -1e30f;
                        if (c0 > rg1) sa[mh][nf][2] = -1e30f;
                        if (c0 + 1 > rg1) sa[mh][nf][3] = -1e30f;
                    }
                }
            }

            // P = exp2(S) -> PV A-fragments (register resident).
            uint32_t pm[2][4][4];
#pragma unroll
            for (int mh = 0; mh < 2; mh++)
#pragma unroll
                for (int nf = 0; nf < 8; nf++) {
                    __half2 a01 =
                        __floats2half2_rn(sa[mh][nf][0], sa[mh][nf][1]);
                    __half2 a23 =
                        __floats2half2_rn(sa[mh][nf][2], sa[mh][nf][3]);
                    pm[mh][nf >> 1][(nf & 1) * 2] =
                        h2ex2(*reinterpret_cast<uint32_t*>(&a01));
                    pm[mh][nf >> 1][(nf & 1) * 2 + 1] =
                        h2ex2(*reinterpret_cast<uint32_t*>(&a23));
                }

            // O += P V ; l += P @ ones. V fragments loaded once per ks.
#pragma unroll
            for (int ks = 0; ks < 4; ks++) {
                uint32_t vq[4][4];
#pragma unroll
                for (int dh = 0; dh < 4; dh++)
                    ldm_x4t(vq[dh],
                            vb + (ks * 16 + l15) * 144 + lhi * 16 + dh * 32);
#pragma unroll
                for (int nf = 0; nf < 8; nf++) {
                    uint32_t b2[2] = {vq[nf >> 1][2 * (nf & 1)],
                                      vq[nf >> 1][2 * (nf & 1) + 1]};
                    mma_f16(of[0][nf], pm[0][ks], b2);
                    mma_f16(of[1][nf], pm[1][ks], b2);
                }
                mma_f16(of[0][8], pm[0][ks], ONES2);
                mma_f16(of[1][8], pm[1][ks], ONES2);
            }
        }
    }

    // Epilogue per m-half.
#pragma unroll
    for (int mh = 0; mh < 2; mh++) {
        const float l0 = __shfl_sync(0xffffffffu, of[mh][8][0], lane & ~3);
        const float l1 = __shfl_sync(0xffffffffu, of[mh][8][2], lane & ~3);
        const float inv0 = 1.f / l0;
        const float inv1 = 1.f / l1;
        float* g0 = out +
            ((size_t)(b * T_) + q0 + rbase + 16 * mh) * (NQ * HD) + h * HD;
        float* g1 = g0 + 8 * (NQ * HD);
#pragma unroll
        for (int nf = 0; nf < 8; nf++) {
            int c = 8 * nf + 2 * tk;
            *reinterpret_cast<float2*>(g0 + c) =
                make_float2(of[mh][nf][0] * inv0, of[mh][nf][1] * inv0);
            *reinterpret_cast<float2*>(g1 + c) =
                make_float2(of[mh][nf][2] * inv1, of[mh][nf][3] * inv1);
        }
    }
}

// ============================ Launch ============================
extern "C" void kernel_launch(void* const* d_in, const int* in_sizes, int n_in,
                              void* d_out, int out_size) {
    (void)in_sizes; (void)n_in; (void)out_size;
    const float* x = (const float*)d_in[0];
    const float* Wq = (const float*)d_in[1];
    const float* Wk = (const float*)d_in[2];
    const float* Wv = (const float*)d_in[3];
    float* out = (float*)d_out;

    __half *xh, *QKVh, *Wth;
    cudaGetSymbolAddress((void**)&xh, g_xh);
    cudaGetSymbolAddress((void**)&QKVh, g_QKVh);
    cudaGetSymbolAddress((void**)&Wth, g_Wth);

    const float sc = 0.125f * 1.4426950408889634f;

    cvt_x<<<(ROWS * D_MODEL) / (256 * 4), 256>>>(x, xh);
    transpose_all<<<dim3(96, 64), dim3(32, 8)>>>(Wq, Wk, Wv, Wth, sc);

    cudaFuncSetAttribute(gemm_h3, cudaFuncAttributeMaxDynamicSharedMemorySize,
                         SMEM_GEMM);
    gemm_h3<<<dim3(QKVW / 128, ROWS / 128), 128, SMEM_GEMM>>>(xh, Wth, QKVh);

    cudaFuncSetAttribute(attn_h, cudaFuncAttributeMaxDynamicSharedMemorySize,
                         SMEM_ATTN);
    dim3 ga(T_ / 128, NQ, B_);
    attn_h<<<ga, 128, SMEM_ATTN>>>(QKVh, out);
}